// round 3
// baseline (speedup 1.0000x reference)
#include <cuda_runtime.h>
#include <math.h>

#define N_COMBOS   64
#define N_STRUCTS  512
#define HID        1024
#define BATCH      2048
#define NITERS     60
#define POW_ITERS  30
#define RB         8
#define RIDX_CAP   6144
#define CI_CAP     8192

// ---------------- device scratch ----------------
__device__ float g_A1[BATCH * HID];
__device__ float g_A2[BATCH * HID];
__device__ float g_Zp[BATCH * N_STRUCTS];      // GEMM3 output, column-PERMUTED (slot space)
__device__ float g_W3p[HID * N_STRUCTS];       // column-permuted W3
__device__ float g_b3p[N_STRUCTS];
__device__ float g_tau;

__device__ int            g_row_ptr[N_COMBOS + 1];
__device__ unsigned short g_row_idx[N_COMBOS * N_STRUCTS];
__device__ int            g_col_ptr[N_STRUCTS + 1];
__device__ unsigned char  g_col_idx[N_COMBOS * N_STRUCTS];

__device__ unsigned short g_rowperm[N_COMBOS];   // slot -> orig row
__device__ unsigned short g_rowslot[N_COMBOS];   // orig row -> slot
__device__ unsigned short g_colperm[N_STRUCTS];  // slot -> orig col
__device__ unsigned short g_colslot[N_STRUCTS];  // orig col -> slot
__device__ int            g_rp4[N_COMBOS + 1];   // ELL step offsets per row-slot
__device__ unsigned short g_ridx4[RIDX_CAP];     // ELL col-slot indices, 4 per step, sentinel 512
__device__ unsigned short g_cp[N_STRUCTS + 1];   // slot CSC offsets (even-padded)
__device__ unsigned char  g_ci[CI_CAP];          // slot CSC row-slot indices, sentinel 64

// ---------------- prep ----------------
__global__ __launch_bounds__(512) void prep_kernel(const float* __restrict__ S,
                                                   const float* __restrict__ W3,
                                                   const float* __restrict__ b3) {
    __shared__ int cnt[N_STRUCTS];
    int tid = threadIdx.x;

    // CSR rows
    if (tid < N_COMBOS) {
        int c = 0;
        for (int j = 0; j < N_STRUCTS; j++) if (S[tid * N_STRUCTS + j] != 0.f) c++;
        cnt[tid] = c;
    }
    __syncthreads();
    if (tid == 0) {
        int acc = 0;
        for (int i = 0; i < N_COMBOS; i++) { g_row_ptr[i] = acc; acc += cnt[i]; }
        g_row_ptr[N_COMBOS] = acc;
    }
    __syncthreads();
    if (tid < N_COMBOS) {
        int p = g_row_ptr[tid];
        for (int j = 0; j < N_STRUCTS; j++)
            if (S[tid * N_STRUCTS + j] != 0.f) g_row_idx[p++] = (unsigned short)j;
    }
    __syncthreads();

    // CSC cols
    {
        int c = 0;
        for (int i = 0; i < N_COMBOS; i++) if (S[i * N_STRUCTS + tid] != 0.f) c++;
        cnt[tid] = c;
    }
    __syncthreads();
    if (tid == 0) {
        int acc = 0;
        for (int j = 0; j < N_STRUCTS; j++) { g_col_ptr[j] = acc; acc += cnt[j]; }
        g_col_ptr[N_STRUCTS] = acc;
    }
    __syncthreads();
    {
        int p = g_col_ptr[tid];
        for (int i = 0; i < N_COMBOS; i++)
            if (S[i * N_STRUCTS + tid] != 0.f) g_col_idx[p++] = (unsigned char)i;
    }
    __syncthreads();

    // row -> warp-slot assignment (balance step counts across 8 warps)
    if (tid == 0) {
        int st[N_COMBOS], ord[N_COMBOS];
        for (int i = 0; i < N_COMBOS; i++) {
            int d = g_row_ptr[i + 1] - g_row_ptr[i];
            int s = (d + 3) >> 2;
            if (s < 1) s = 1;
            if (s > 24) s = 24;            // cap (RIDX_CAP/4/64)
            st[i] = s; ord[i] = i;
        }
        for (int a = 0; a < N_COMBOS; a++) {         // selection sort desc
            int best = a;
            for (int bb = a + 1; bb < N_COMBOS; bb++)
                if (st[ord[bb]] > st[ord[best]]) best = bb;
            int t = ord[a]; ord[a] = ord[best]; ord[best] = t;
        }
        int load[8] = {0,0,0,0,0,0,0,0};
        int wc[8]   = {0,0,0,0,0,0,0,0};
        for (int s = 0; s < N_COMBOS; s++) {
            int i = ord[s];
            int w = -1;
            for (int k = 0; k < 8; k++)
                if (wc[k] < 8 && (w < 0 || load[k] < load[w])) w = k;
            int slot = w * 8 + wc[w]; wc[w]++;
            load[w] += st[i];
            g_rowperm[slot] = (unsigned short)i;
            g_rowslot[i]    = (unsigned short)slot;
        }
        int acc = 0;
        for (int slot = 0; slot < N_COMBOS; slot++) {
            g_rp4[slot] = acc; acc += st[g_rowperm[slot]];
        }
        g_rp4[N_COMBOS] = acc;
    }

    // col -> slot assignment (sort by padded pair-count, group equal degrees into
    // co-scheduled quadruples {4w+k+32q})
    if (tid == 0) {
        int pd[N_STRUCTS];
        for (int j = 0; j < N_STRUCTS; j++) {
            int d = g_col_ptr[j + 1] - g_col_ptr[j];
            pd[j] = (d + 1) >> 1;
        }
        int s = 0;
        for (int v = 64; v >= 0; v--) {
            for (int j = 0; j < N_STRUCTS; j++) if (pd[j] == v) {
                int g = s >> 2, k = s & 3;
                int w = g & 7, q = g >> 3;
                int slot = 4 * w + k + 32 * q;
                g_colperm[slot] = (unsigned short)j;
                g_colslot[j]    = (unsigned short)slot;
                s++;
            }
        }
        int acc = 0;
        for (int slot = 0; slot < N_STRUCTS; slot++) {
            g_cp[slot] = (unsigned short)acc;
            int e = 2 * pd[g_colperm[slot]];
            if (acc + e > CI_CAP) e = 0;   // defensive
            acc += e;
        }
        g_cp[N_STRUCTS] = (unsigned short)acc;
    }
    __syncthreads();

    // slot CSC (parallel, 512 threads)
    {
        int js = tid;
        int j = g_colperm[js];
        int o = g_cp[js];
        int base = g_col_ptr[j];
        int d = g_col_ptr[j + 1] - base;
        int e = (int)g_cp[js + 1] - o;
        for (int p = 0; p < e; p++)
            g_ci[o + p] = (p < d) ? (unsigned char)g_rowslot[g_col_idx[base + p]]
                                  : (unsigned char)64;
    }
    __syncthreads();

    // row ELL with mod-4 class round-robin (64 threads)
    if (tid < N_COMBOS) {
        int i = tid;
        int slot = g_rowslot[i];
        int base = g_rp4[slot] * 4;
        int steps = g_rp4[slot + 1] - g_rp4[slot];
        unsigned short bk[4][144];
        int bc[4] = {0,0,0,0};
        int p0 = g_row_ptr[i], p1 = g_row_ptr[i + 1];
        for (int p = p0; p < p1; p++) {
            int js = g_colslot[g_row_idx[p]];
            int c = js & 3;
            if (bc[c] < 144) bk[c][bc[c]++] = (unsigned short)js;
        }
        int ptr4[4] = {0,0,0,0};
        for (int s = 0; s < steps; s++) {
            for (int k = 0; k < 4; k++) {
                int c = k;
                if (ptr4[c] >= bc[c]) {
                    int best = -1, rem = 0;
                    for (int cc = 0; cc < 4; cc++) {
                        int r = bc[cc] - ptr4[cc];
                        if (r > rem) { rem = r; best = cc; }
                    }
                    c = best;
                }
                unsigned short v = 512;
                if (c >= 0 && ptr4[c] < bc[c]) v = bk[c][ptr4[c]++];
                g_ridx4[base + s * 4 + k] = v;
            }
        }
    }

    // W3/b3 column permute (parallel)
    for (int e = tid; e < HID * N_STRUCTS; e += 512) {
        int h = e >> 9, js = e & 511;
        g_W3p[e] = W3[h * N_STRUCTS + g_colperm[js]];
    }
    if (tid < N_STRUCTS) g_b3p[tid] = b3[g_colperm[tid]];
}

// ---------------- power iteration (original structures) ----------------
__global__ __launch_bounds__(512) void power_kernel() {
    __shared__ float v[N_STRUCTS];
    __shared__ float t[N_COMBOS];
    __shared__ float red[16];
    int tid = threadIdx.x;

    v[tid] = 1.0f / sqrtf((float)N_STRUCTS);
    __syncthreads();

    for (int it = 0; it < POW_ITERS; it++) {
        if (tid < N_COMBOS) {
            float s = 0.f;
            int pe = g_row_ptr[tid + 1];
            for (int p = g_row_ptr[tid]; p < pe; p++) s += v[g_row_idx[p]];
            t[tid] = s;
        }
        __syncthreads();
        float w;
        {
            float s = 0.f;
            int pe = g_col_ptr[tid + 1];
            for (int p = g_col_ptr[tid]; p < pe; p++) s += t[g_col_idx[p]];
            w = s + v[tid];
        }
        float sq = w * w;
        #pragma unroll
        for (int o = 16; o; o >>= 1) sq += __shfl_xor_sync(0xffffffffu, sq, o);
        if ((tid & 31) == 0) red[tid >> 5] = sq;
        __syncthreads();
        float tot = 0.f;
        #pragma unroll
        for (int k = 0; k < 16; k++) tot += red[k];
        v[tid] = w / sqrtf(tot);
        __syncthreads();
    }

    if (tid < N_COMBOS) {
        float s = 0.f;
        int pe = g_row_ptr[tid + 1];
        for (int p = g_row_ptr[tid]; p < pe; p++) s += v[g_row_idx[p]];
        t[tid] = s;
    }
    __syncthreads();
    float w;
    {
        float s = 0.f;
        int pe = g_col_ptr[tid + 1];
        for (int p = g_col_ptr[tid]; p < pe; p++) s += t[g_col_idx[p]];
        w = s + v[tid];
    }
    float dq = v[tid] * w;
    #pragma unroll
    for (int o = 16; o; o >>= 1) dq += __shfl_xor_sync(0xffffffffu, dq, o);
    if ((tid & 31) == 0) red[tid >> 5] = dq;
    __syncthreads();
    if (tid == 0) {
        float tot = 0.f;
        #pragma unroll
        for (int k = 0; k < 16; k++) tot += red[k];
        g_tau = 0.9f / sqrtf(tot);
    }
}

// ---------------- GEMM + bias + relu (64x64x16, 128 threads) ----------------
__global__ __launch_bounds__(128) void gemm_bias_relu(
    const float* __restrict__ A, const float* __restrict__ B,
    const float* __restrict__ bias, float* __restrict__ C,
    int M, int N, int K)
{
    const int BM = 64, BN = 64, BK = 16;
    __shared__ __align__(16) float As[BK][BM];
    __shared__ __align__(16) float Bs[BK][BN];

    const int tid = threadIdx.x;
    const int bm = blockIdx.y * BM;
    const int bn = blockIdx.x * BN;

    const int a_r = tid >> 1, a_c = (tid & 1) * 8;
    const int b_r = tid >> 3, b_c = (tid & 7) * 8;
    const int tx = tid & 15, ty = tid >> 4;

    float acc[8][4];
    #pragma unroll
    for (int i = 0; i < 8; i++)
        #pragma unroll
        for (int j = 0; j < 4; j++) acc[i][j] = 0.f;

    for (int k0 = 0; k0 < K; k0 += BK) {
        float4 av0 = *(const float4*)&A[(size_t)(bm + a_r) * K + k0 + a_c];
        float4 av1 = *(const float4*)&A[(size_t)(bm + a_r) * K + k0 + a_c + 4];
        As[a_c + 0][a_r] = av0.x; As[a_c + 1][a_r] = av0.y;
        As[a_c + 2][a_r] = av0.z; As[a_c + 3][a_r] = av0.w;
        As[a_c + 4][a_r] = av1.x; As[a_c + 5][a_r] = av1.y;
        As[a_c + 6][a_r] = av1.z; As[a_c + 7][a_r] = av1.w;
        float4 bv0 = *(const float4*)&B[(size_t)(k0 + b_r) * N + bn + b_c];
        float4 bv1 = *(const float4*)&B[(size_t)(k0 + b_r) * N + bn + b_c + 4];
        *(float4*)&Bs[b_r][b_c] = bv0;
        *(float4*)&Bs[b_r][b_c + 4] = bv1;
        __syncthreads();

        #pragma unroll
        for (int k = 0; k < BK; k++) {
            float4 a0 = *(const float4*)&As[k][ty * 8];
            float4 a1 = *(const float4*)&As[k][ty * 8 + 4];
            float4 b0 = *(const float4*)&Bs[k][tx * 4];
            float a[8] = {a0.x, a0.y, a0.z, a0.w, a1.x, a1.y, a1.z, a1.w};
            float bb[4] = {b0.x, b0.y, b0.z, b0.w};
            #pragma unroll
            for (int i = 0; i < 8; i++)
                #pragma unroll
                for (int j = 0; j < 4; j++)
                    acc[i][j] = fmaf(a[i], bb[j], acc[i][j]);
        }
        __syncthreads();
    }

    #pragma unroll
    for (int j = 0; j < 4; j++) {
        float bb = bias[bn + tx * 4 + j];
        #pragma unroll
        for (int i = 0; i < 8; i++) {
            float r = acc[i][j] + bb;
            C[(size_t)(bm + ty * 8 + i) * N + bn + tx * 4 + j] = r > 0.f ? r : 0.f;
        }
    }
}

// ---------------- PDHG: batch-minor, 8 rows per block ----------------
__global__ __launch_bounds__(256, 2) void pdhg_kernel(
    const float* __restrict__ Zp, const float* __restrict__ Xg,
    float* __restrict__ out)
{
    __shared__ float sx[N_STRUCTS + 1][RB];     // [col-slot][b], row 512 = sentinel 0
    __shared__ float sy1[N_COMBOS + 1][RB];     // [row-slot][b], row 64 = sentinel 0
    __shared__ float sB[N_COMBOS][RB];
    __shared__ float sred[8][8];
    __shared__ int            s_rp[N_COMBOS + 1];
    __shared__ unsigned short s_ridx[RIDX_CAP];
    __shared__ unsigned short s_cp[N_STRUCTS + 1];
    __shared__ unsigned char  s_ci[CI_CAP];

    const int tid = threadIdx.x;
    const int w = tid >> 5, l = tid & 31;
    const int b = tid & 7, jg = tid >> 3;       // elementwise: slot = jg + 32*q
    const int bl = l & 7, jj4 = l >> 3;         // row gather lanes
    const int row0 = blockIdx.x * RB;
    const float tau = g_tau, sigma = tau;

    const int nst4 = g_rp4[N_COMBOS] * 4;
    const int nci  = g_cp[N_STRUCTS];
    for (int p = tid; p <= N_COMBOS; p += 256) s_rp[p] = g_rp4[p];
    for (int p = tid; p < nst4; p += 256) s_ridx[p] = g_ridx4[p];
    for (int p = tid; p <= N_STRUCTS; p += 256) s_cp[p] = g_cp[p];
    for (int p = tid; p < nci; p += 256) s_ci[p] = g_ci[p];
    for (int p = tid; p < N_COMBOS * RB; p += 256) {
        int slot = p >> 3, bb = p & 7;
        sB[slot][bb] = Xg[(row0 + bb) * N_COMBOS + g_rowperm[slot]];
    }
    for (int p = tid; p < (N_COMBOS + 1) * RB; p += 256) ((float*)sy1)[p] = 0.f;
    for (int p = tid; p < (N_STRUCTS + 1) * RB; p += 256) ((float*)sx)[p] = 0.f;

    float Zr[16], xr[16], y2[16], dd[16], xb[16];
    #pragma unroll
    for (int q = 0; q < 16; q++) {
        Zr[q] = Zp[(size_t)(row0 + b) * N_STRUCTS + jg + 32 * q];
        xr[q] = 0.f; y2[q] = 0.f; xb[q] = 0.f;
    }
    __syncthreads();

    for (int it = 0; it < NITERS; it++) {
        // ---- y1 = max(y1 + sigma*(S xbar - B), 0) : 8 row-slots per warp ----
        for (int r = 0; r < 8; r++) {
            int i = w * 8 + r;
            int s0 = s_rp[i], s1 = s_rp[i + 1];
            float acc = 0.f;
            #pragma unroll 4
            for (int s = s0; s < s1; s++) {
                int j = s_ridx[s * 4 + jj4];
                acc += sx[j][bl];
            }
            acc += __shfl_down_sync(0xffffffffu, acc, 16);
            acc += __shfl_down_sync(0xffffffffu, acc, 8);
            if (l < 8) {
                float yv = sy1[i][l];
                yv = fmaxf(fmaf(sigma, acc - sB[i][l], yv), 0.f);
                sy1[i][l] = yv;
            }
        }
        // ---- y2 = max(y2 - sigma*xbar, 0) (registers) ----
        #pragma unroll
        for (int q = 0; q < 16; q++)
            y2[q] = fmaxf(fmaf(-sigma, xb[q], y2[q]), 0.f);
        __syncthreads();

        // ---- g = S^T y1 - y2 ; prox prep ----
        const unsigned short* ci16 = (const unsigned short*)s_ci;
        float sumsq = 0.f;
        #pragma unroll
        for (int q = 0; q < 16; q++) {
            int js = jg + 32 * q;
            int p0 = s_cp[js] >> 1, p1 = s_cp[js + 1] >> 1;
            float gs = 0.f;
            #pragma unroll 2
            for (int p = p0; p < p1; p++) {
                unsigned u = ci16[p];
                gs += sy1[u & 255u][b] + sy1[u >> 8][b];
            }
            gs -= y2[q];
            float v = fmaf(-tau, gs, xr[q]);
            float d1 = v + tau - Zr[q];
            dd[q] = d1;
            sumsq = fmaf(d1, d1, sumsq);
        }
        sumsq += __shfl_down_sync(0xffffffffu, sumsq, 16);
        sumsq += __shfl_down_sync(0xffffffffu, sumsq, 8);
        if (l < 8) sred[w][l] = sumsq;
        __syncthreads();

        float tot = 0.f;
        #pragma unroll
        for (int ww = 0; ww < 8; ww++) tot += sred[ww][b];
        float scale = fmaxf(1.f - tau / fmaxf(sqrtf(tot), 1e-12f), 0.f);

        #pragma unroll
        for (int q = 0; q < 16; q++) {
            float xn  = fmaf(scale, dd[q], Zr[q]);
            float xbv = 2.f * xn - xr[q];
            xr[q] = xn; xb[q] = xbv;
            sx[jg + 32 * q][b] = xbv;
        }
        __syncthreads();
    }

    #pragma unroll
    for (int q = 0; q < 16; q++)
        out[(size_t)(row0 + b) * N_STRUCTS + g_colperm[jg + 32 * q]] = xr[q];
}

// ---------------- launch ----------------
extern "C" void kernel_launch(void* const* d_in, const int* in_sizes, int n_in,
                              void* d_out, int out_size) {
    const float* X  = (const float*)d_in[0];
    const float* W1 = (const float*)d_in[1];
    const float* b1 = (const float*)d_in[2];
    const float* W2 = (const float*)d_in[3];
    const float* b2 = (const float*)d_in[4];
    const float* W3 = (const float*)d_in[5];
    const float* b3 = (const float*)d_in[6];
    const float* S  = (const float*)d_in[7];
    float* out = (float*)d_out;

    float *A1, *A2, *Zp, *W3p, *b3p;
    cudaGetSymbolAddress((void**)&A1,  g_A1);
    cudaGetSymbolAddress((void**)&A2,  g_A2);
    cudaGetSymbolAddress((void**)&Zp,  g_Zp);
    cudaGetSymbolAddress((void**)&W3p, g_W3p);
    cudaGetSymbolAddress((void**)&b3p, g_b3p);

    prep_kernel<<<1, 512>>>(S, W3, b3);
    power_kernel<<<1, 512>>>();

    gemm_bias_relu<<<dim3(HID / 64, BATCH / 64), 128>>>(X, W1, b1, A1, BATCH, HID, N_COMBOS);
    gemm_bias_relu<<<dim3(HID / 64, BATCH / 64), 128>>>(A1, W2, b2, A2, BATCH, HID, HID);
    gemm_bias_relu<<<dim3(N_STRUCTS / 64, BATCH / 64), 128>>>(A2, W3p, b3p, Zp, BATCH, N_STRUCTS, HID);

    pdhg_kernel<<<BATCH / RB, 256>>>(Zp, X, out);
}

// round 4
// speedup vs baseline: 1.4660x; 1.4660x over previous
#include <cuda_runtime.h>
#include <math.h>

#define N_COMBOS   64
#define N_STRUCTS  512
#define HID        1024
#define BATCH      2048
#define NITERS     60
#define POW_ITERS  30

#define MAX_NNZ_G  32768
#define MAX_LR     96
#define COLCAP     8192
#define ROWS_PER_BLK 8

// ---------------- device scratch ----------------
__device__ float g_A1[BATCH * HID];
__device__ float g_A2[BATCH * HID];
__device__ float g_Z [BATCH * N_STRUCTS];
__device__ float g_tau;

__device__ int            g_row_ptr[N_COMBOS + 1];
__device__ unsigned short g_row_idx[MAX_NNZ_G];
__device__ int            g_col_ptr[N_STRUCTS + 1];
__device__ unsigned char  g_col_idx[MAX_NNZ_G];

__device__ unsigned short g_row_ord[N_COMBOS * MAX_LR];  // bank-targeted per-row order
__device__ unsigned int   g_ellr[MAX_LR * 32];           // [p][lane]: rowL | rowL+32<<16 ; sentinel 512
__device__ int            g_len_ellr;
__device__ unsigned short g_cp4[N_STRUCTS + 1];          // padded (mult of 4) CSC offsets
__device__ unsigned char  g_ci4[COLCAP];                 // padded CSC indices, bank-targeted order; sentinel 64

// ---------------- prep: CSR + CSC + bank-aware packed ELL/CSC4 ----------------
__global__ __launch_bounds__(512) void prep_kernel(const float* __restrict__ S) {
    __shared__ int cnt[N_STRUCTS];
    int tid = threadIdx.x;

    // CSR rows (64)
    if (tid < N_COMBOS) {
        int c = 0;
        for (int j = 0; j < N_STRUCTS; j++) if (S[tid * N_STRUCTS + j] != 0.f) c++;
        cnt[tid] = c;
    }
    __syncthreads();
    if (tid == 0) {
        int acc = 0;
        for (int i = 0; i < N_COMBOS; i++) { g_row_ptr[i] = acc; acc += cnt[i]; }
        g_row_ptr[N_COMBOS] = acc;
    }
    __syncthreads();
    if (tid < N_COMBOS) {
        int p = g_row_ptr[tid];
        for (int j = 0; j < N_STRUCTS; j++)
            if (S[tid * N_STRUCTS + j] != 0.f) g_row_idx[p++] = (unsigned short)j;
    }
    __syncthreads();

    // CSC cols (512)
    {
        int c = 0;
        for (int i = 0; i < N_COMBOS; i++) if (S[i * N_STRUCTS + tid] != 0.f) c++;
        cnt[tid] = c;
    }
    __syncthreads();
    if (tid == 0) {
        int acc = 0;
        for (int j = 0; j < N_STRUCTS; j++) { g_col_ptr[j] = acc; acc += cnt[j]; }
        g_col_ptr[N_STRUCTS] = acc;
    }
    __syncthreads();
    {
        int p = g_col_ptr[tid];
        for (int i = 0; i < N_COMBOS; i++)
            if (S[i * N_STRUCTS + tid] != 0.f) g_col_idx[p++] = (unsigned char)i;
    }
    __syncthreads();

    // ---- per-row bank-targeted reorder (64 threads, independent) ----
    if (tid < N_COMBOS) {
        int base = g_row_ptr[tid];
        int deg = g_row_ptr[tid + 1] - base;
        if (deg > MAX_LR) deg = MAX_LR;
        unsigned short tmp[MAX_LR];
        int bcnt[32], bptr[32], brem[32];
        #pragma unroll
        for (int k = 0; k < 32; k++) bcnt[k] = 0;
        for (int p = 0; p < deg; p++) bcnt[g_row_idx[base + p] & 31]++;
        int acc = 0;
        #pragma unroll
        for (int k = 0; k < 32; k++) { bptr[k] = acc; acc += bcnt[k]; brem[k] = bcnt[k]; }
        {
            int cur[32];
            #pragma unroll
            for (int k = 0; k < 32; k++) cur[k] = bptr[k];
            for (int p = 0; p < deg; p++) {
                unsigned short v = g_row_idx[base + p];
                tmp[cur[v & 31]++] = v;
            }
        }
        int l = tid & 31;
        for (int p = 0; p < deg; p++) {
            int d = (l + p) & 31, k = 0;
            while (brem[(d + k) & 31] == 0) k++;
            int bb = (d + k) & 31;
            g_row_ord[tid * MAX_LR + p] = tmp[bptr[bb]++];
            brem[bb]--;
        }
    }

    // padded CSC offsets (thread 0, cheap: 512 iters)
    if (tid == 0) {
        int acc = 0;
        for (int j = 0; j < N_STRUCTS; j++) {
            g_cp4[j] = (unsigned short)acc;
            int l = g_col_ptr[j + 1] - g_col_ptr[j];
            acc += (l + 3) & ~3;
        }
        g_cp4[N_STRUCTS] = (unsigned short)acc;
    }
    __syncthreads();

    // ---- per-col bank-targeted reorder into g_ci4 (512 threads, independent) ----
    {
        int j = tid;
        int o = g_cp4[j];
        int base = g_col_ptr[j];
        int deg = g_col_ptr[j + 1] - base;
        int pl = (int)g_cp4[j + 1] - o;
        unsigned char tmp[32];
        int bcnt[32], bptr[32], brem[32];
        #pragma unroll
        for (int k = 0; k < 32; k++) bcnt[k] = 0;
        if (deg > 32) deg = 32;
        for (int p = 0; p < deg; p++) bcnt[g_col_idx[base + p] & 31]++;
        int acc = 0;
        #pragma unroll
        for (int k = 0; k < 32; k++) { bptr[k] = acc; acc += bcnt[k]; brem[k] = bcnt[k]; }
        {
            int cur[32];
            #pragma unroll
            for (int k = 0; k < 32; k++) cur[k] = bptr[k];
            for (int p = 0; p < deg; p++) {
                unsigned char v = g_col_idx[base + p];
                tmp[cur[v & 31]++] = v;
            }
        }
        int l = j & 31;
        for (int p = 0; p < pl; p++) {
            unsigned char v = 64;
            if (p < deg) {
                int d = (l + p) & 31, k = 0;
                while (brem[(d + k) & 31] == 0) k++;
                int bb = (d + k) & 31;
                v = tmp[bptr[bb]++];
                brem[bb]--;
            }
            if (o + p < COLCAP) g_ci4[o + p] = v;
        }
    }
    __syncthreads();

    // ---- pack row-pair ELL from ordered lists (32 threads) ----
    if (tid < 32) {
        int la = g_row_ptr[tid + 1] - g_row_ptr[tid];
        int lb = g_row_ptr[tid + 33] - g_row_ptr[tid + 32];
        if (la > MAX_LR) la = MAX_LR;
        if (lb > MAX_LR) lb = MAX_LR;
        int L = la > lb ? la : lb;
        for (int p = 0; p < MAX_LR; p++) {
            unsigned a = (p < la) ? g_row_ord[tid * MAX_LR + p] : 512u;
            unsigned b = (p < lb) ? g_row_ord[(tid + 32) * MAX_LR + p] : 512u;
            g_ellr[p * 32 + tid] = a | (b << 16);
        }
        #pragma unroll
        for (int o = 16; o; o >>= 1) { int v = __shfl_xor_sync(0xffffffffu, L, o); L = v > L ? v : L; }
        if (tid == 0) g_len_ellr = L;
    }
}

// ---------------- power iteration: tau = 0.9 / ||K||_2 ----------------
__global__ __launch_bounds__(512) void power_kernel() {
    __shared__ float v[N_STRUCTS];
    __shared__ float t[N_COMBOS];
    __shared__ float red[16];
    int tid = threadIdx.x;

    v[tid] = 1.0f / sqrtf((float)N_STRUCTS);
    __syncthreads();

    for (int it = 0; it < POW_ITERS; it++) {
        if (tid < N_COMBOS) {
            float s = 0.f;
            int pe = g_row_ptr[tid + 1];
            for (int p = g_row_ptr[tid]; p < pe; p++) s += v[g_row_idx[p]];
            t[tid] = s;
        }
        __syncthreads();
        float w;
        {
            float s = 0.f;
            int pe = g_col_ptr[tid + 1];
            for (int p = g_col_ptr[tid]; p < pe; p++) s += t[g_col_idx[p]];
            w = s + v[tid];
        }
        float sq = w * w;
        #pragma unroll
        for (int o = 16; o; o >>= 1) sq += __shfl_xor_sync(0xffffffffu, sq, o);
        if ((tid & 31) == 0) red[tid >> 5] = sq;
        __syncthreads();
        float tot = 0.f;
        #pragma unroll
        for (int k = 0; k < 16; k++) tot += red[k];
        v[tid] = w / sqrtf(tot);
        __syncthreads();
    }

    if (tid < N_COMBOS) {
        float s = 0.f;
        int pe = g_row_ptr[tid + 1];
        for (int p = g_row_ptr[tid]; p < pe; p++) s += v[g_row_idx[p]];
        t[tid] = s;
    }
    __syncthreads();
    float w;
    {
        float s = 0.f;
        int pe = g_col_ptr[tid + 1];
        for (int p = g_col_ptr[tid]; p < pe; p++) s += t[g_col_idx[p]];
        w = s + v[tid];
    }
    float dq = v[tid] * w;
    #pragma unroll
    for (int o = 16; o; o >>= 1) dq += __shfl_xor_sync(0xffffffffu, dq, o);
    if ((tid & 31) == 0) red[tid >> 5] = dq;
    __syncthreads();
    if (tid == 0) {
        float tot = 0.f;
        #pragma unroll
        for (int k = 0; k < 16; k++) tot += red[k];
        g_tau = 0.9f / sqrtf(tot);
    }
}

// ---------------- GEMM + bias + relu (64x64x16, 128 threads, 8x4 tile) ----------------
__global__ __launch_bounds__(128) void gemm_bias_relu(
    const float* __restrict__ A, const float* __restrict__ B,
    const float* __restrict__ bias, float* __restrict__ C,
    int M, int N, int K)
{
    const int BM = 64, BN = 64, BK = 16;
    __shared__ __align__(16) float As[BK][BM];
    __shared__ __align__(16) float Bs[BK][BN];

    const int tid = threadIdx.x;
    const int bm = blockIdx.y * BM;
    const int bn = blockIdx.x * BN;

    const int a_r = tid >> 1, a_c = (tid & 1) * 8;
    const int b_r = tid >> 3, b_c = (tid & 7) * 8;
    const int tx = tid & 15, ty = tid >> 4;

    float acc[8][4];
    #pragma unroll
    for (int i = 0; i < 8; i++)
        #pragma unroll
        for (int j = 0; j < 4; j++) acc[i][j] = 0.f;

    for (int k0 = 0; k0 < K; k0 += BK) {
        float4 av0 = *(const float4*)&A[(size_t)(bm + a_r) * K + k0 + a_c];
        float4 av1 = *(const float4*)&A[(size_t)(bm + a_r) * K + k0 + a_c + 4];
        As[a_c + 0][a_r] = av0.x; As[a_c + 1][a_r] = av0.y;
        As[a_c + 2][a_r] = av0.z; As[a_c + 3][a_r] = av0.w;
        As[a_c + 4][a_r] = av1.x; As[a_c + 5][a_r] = av1.y;
        As[a_c + 6][a_r] = av1.z; As[a_c + 7][a_r] = av1.w;
        float4 bv0 = *(const float4*)&B[(size_t)(k0 + b_r) * N + bn + b_c];
        float4 bv1 = *(const float4*)&B[(size_t)(k0 + b_r) * N + bn + b_c + 4];
        *(float4*)&Bs[b_r][b_c] = bv0;
        *(float4*)&Bs[b_r][b_c + 4] = bv1;
        __syncthreads();

        #pragma unroll
        for (int k = 0; k < BK; k++) {
            float4 a0 = *(const float4*)&As[k][ty * 8];
            float4 a1 = *(const float4*)&As[k][ty * 8 + 4];
            float4 b0 = *(const float4*)&Bs[k][tx * 4];
            float a[8] = {a0.x, a0.y, a0.z, a0.w, a1.x, a1.y, a1.z, a1.w};
            float bb[4] = {b0.x, b0.y, b0.z, b0.w};
            #pragma unroll
            for (int i = 0; i < 8; i++)
                #pragma unroll
                for (int j = 0; j < 4; j++)
                    acc[i][j] = fmaf(a[i], bb[j], acc[i][j]);
        }
        __syncthreads();
    }

    #pragma unroll
    for (int j = 0; j < 4; j++) {
        float bb = bias[bn + tx * 4 + j];
        #pragma unroll
        for (int i = 0; i < 8; i++) {
            float r = acc[i][j] + bb;
            C[(size_t)(bm + ty * 8 + i) * N + bn + tx * 4 + j] = r > 0.f ? r : 0.f;
        }
    }
}

// ---------------- PDHG: one WARP per batch row, 8 warps per block ----------------
__global__ __launch_bounds__(256, 2) void pdhg_warp_kernel(
    const float* __restrict__ Zg, const float* __restrict__ Xg,
    float* __restrict__ out)
{
    constexpr int XB = 516;
    __shared__ unsigned int   s_ellr[MAX_LR * 32];
    __shared__ unsigned short s_cp4[N_STRUCTS + 2];
    __shared__ unsigned char  s_ci4[COLCAP];
    __shared__ float          s_xbar[ROWS_PER_BLK][XB];
    __shared__ float          s_y1[ROWS_PER_BLK][68];

    const int tid = threadIdx.x;
    const int w   = tid >> 5;
    const int l   = tid & 31;
    const int row = blockIdx.x * ROWS_PER_BLK + w;
    const float tau = g_tau;
    const float sigma = tau;
    const int LEN = g_len_ellr;

    for (int p = tid; p < LEN * 32; p += 256) s_ellr[p] = g_ellr[p];
    for (int p = tid; p <= N_STRUCTS; p += 256) s_cp4[p] = g_cp4[p];
    {
        int tot = (g_cp4[N_STRUCTS] + 3) & ~3;
        for (int p = tid * 4; p < tot; p += 1024)
            *(unsigned int*)&s_ci4[p] = *(const unsigned int*)&g_ci4[p];
    }

    float* sx  = s_xbar[w];
    float* sy1 = s_y1[w];

    const float B0 = Xg[row * N_COMBOS + l];
    const float B1 = Xg[row * N_COMBOS + l + 32];
    float yy0 = 0.f, yy1 = 0.f;

    float Zr[16], xr[16], y2[16], xb[16], dq[16];
    #pragma unroll
    for (int q = 0; q < 16; q++) {
        int j = q * 32 + l;
        Zr[q] = Zg[(size_t)row * N_STRUCTS + j];
        xr[q] = 0.f; y2[q] = 0.f; xb[q] = 0.f;
        sx[j] = 0.f;
    }
    if (l < XB - 512) sx[512 + l] = 0.f;
    if (l < 4) sy1[64 + l] = 0.f;
    __syncthreads();

    for (int it = 0; it < NITERS; it++) {
        // ---- y1 = max(y1 + sigma*(S xbar - B), 0): row-pair gather ----
        float s0 = 0.f, s1 = 0.f;
        for (int p = 0; p < LEN; p++) {
            unsigned u = s_ellr[p * 32 + l];
            s0 += sx[u & 0xffffu];
            s1 += sx[u >> 16];
        }
        yy0 = fmaxf(fmaf(sigma, s0 - B0, yy0), 0.f);
        yy1 = fmaxf(fmaf(sigma, s1 - B1, yy1), 0.f);
        sy1[l] = yy0;
        sy1[l + 32] = yy1;

        // ---- y2 = max(y2 - sigma*xbar, 0) ----
        #pragma unroll
        for (int q = 0; q < 16; q++)
            y2[q] = fmaxf(fmaf(-sigma, xb[q], y2[q]), 0.f);
        __syncwarp();

        // ---- g = S^T y1 - y2 ; prox ----
        float sumsq = 0.f;
        #pragma unroll
        for (int q = 0; q < 16; q++) {
            int j = q * 32 + l;
            int o = s_cp4[j], e = s_cp4[j + 1];
            float g = 0.f;
            for (int p = o; p < e; p += 4) {
                unsigned w4 = *(const unsigned int*)&s_ci4[p];
                g += sy1[w4 & 255u] + sy1[(w4 >> 8) & 255u]
                   + sy1[(w4 >> 16) & 255u] + sy1[w4 >> 24];
            }
            g -= y2[q];
            float v = fmaf(-tau, g, xr[q]);
            float d = v + tau - Zr[q];
            dq[q] = d;
            sumsq = fmaf(d, d, sumsq);
        }
        #pragma unroll
        for (int o = 16; o; o >>= 1) sumsq += __shfl_xor_sync(0xffffffffu, sumsq, o);
        float nrm = sqrtf(sumsq);
        float scale = fmaxf(1.f - tau / fmaxf(nrm, 1e-12f), 0.f);

        #pragma unroll
        for (int q = 0; q < 16; q++) {
            int j = q * 32 + l;
            float xn  = fmaf(scale, dq[q], Zr[q]);
            float xbv = 2.f * xn - xr[q];
            xr[q] = xn;
            xb[q] = xbv;
            sx[j] = xbv;
        }
        __syncwarp();
    }

    #pragma unroll
    for (int q = 0; q < 16; q++)
        out[(size_t)row * N_STRUCTS + q * 32 + l] = xr[q];
}

// ---------------- launch ----------------
extern "C" void kernel_launch(void* const* d_in, const int* in_sizes, int n_in,
                              void* d_out, int out_size) {
    const float* X  = (const float*)d_in[0];
    const float* W1 = (const float*)d_in[1];
    const float* b1 = (const float*)d_in[2];
    const float* W2 = (const float*)d_in[3];
    const float* b2 = (const float*)d_in[4];
    const float* W3 = (const float*)d_in[5];
    const float* b3 = (const float*)d_in[6];
    const float* S  = (const float*)d_in[7];
    float* out = (float*)d_out;

    float *A1, *A2, *Z;
    cudaGetSymbolAddress((void**)&A1, g_A1);
    cudaGetSymbolAddress((void**)&A2, g_A2);
    cudaGetSymbolAddress((void**)&Z,  g_Z);

    prep_kernel<<<1, 512>>>(S);
    power_kernel<<<1, 512>>>();

    gemm_bias_relu<<<dim3(HID / 64, BATCH / 64), 128>>>(X, W1, b1, A1, BATCH, HID, N_COMBOS);
    gemm_bias_relu<<<dim3(HID / 64, BATCH / 64), 128>>>(A1, W2, b2, A2, BATCH, HID, HID);
    gemm_bias_relu<<<dim3(N_STRUCTS / 64, BATCH / 64), 128>>>(A2, W3, b3, Z, BATCH, N_STRUCTS, HID);

    pdhg_warp_kernel<<<BATCH / ROWS_PER_BLK, 256>>>(Z, X, out);
}